// round 2
// baseline (speedup 1.0000x reference)
#include <cuda_runtime.h>
#include <cuda_fp16.h>
#include <cstdint>

// ============================================================================
// Reduction: softmax over length-1 key axis == 1  =>  attended = V-projection.
//   a1 = LN( v2 @ (Wo1@Wv2)^T + (Wo1@bv2 + bo1) + v1 ; g1, be1 )
//   a2 = LN( v1 @ (Wo2@Wv1)^T + (Wo2@bv1 + bo2) + v2 ; g2, be2 )
// GEMMs via mma.sync fp16 (single pass; error ~2e-4 of output).
// Residual reconstructed from fp16 hi+lo (error ~2^-22).
// No tcgen05 — harness compiles at compute_103 (no 'a' features).
// ============================================================================

#define EMBED 64
#define TILE_M 128
#define STRIDE 72  // fp16 elems per smem row (pad 64->72: conflict-free frags)

// ---------------- device scratch for folded weights -------------------------
__device__ __half g_M[2][EMBED * EMBED];   // [j][k] row-major, fp16
__device__ float  g_bias[2][EMBED];

// ---------------- prep: fold Wo@Wv -> fp16, Wo@bv + bo -> f32 ---------------
__global__ void prep_kernel(const float* __restrict__ Wo1, const float* __restrict__ Wv2,
                            const float* __restrict__ bv2, const float* __restrict__ bo1,
                            const float* __restrict__ Wo2, const float* __restrict__ Wv1,
                            const float* __restrict__ bv1, const float* __restrict__ bo2) {
    int t = threadIdx.x;
    for (int idx = t; idx < EMBED * EMBED; idx += blockDim.x) {
        int j = idx >> 6, k = idx & 63;
        float s1 = 0.f, s2 = 0.f;
#pragma unroll 8
        for (int i = 0; i < EMBED; i++) {
            s1 = fmaf(Wo1[j * 64 + i], Wv2[i * 64 + k], s1);
            s2 = fmaf(Wo2[j * 64 + i], Wv1[i * 64 + k], s2);
        }
        g_M[0][idx] = __float2half_rn(s1);
        g_M[1][idx] = __float2half_rn(s2);
    }
    if (t < EMBED) {
        float s1 = bo1[t], s2 = bo2[t];
#pragma unroll 8
        for (int i = 0; i < EMBED; i++) {
            s1 = fmaf(Wo1[t * 64 + i], bv2[i], s1);
            s2 = fmaf(Wo2[t * 64 + i], bv1[i], s2);
        }
        g_bias[0][t] = s1;
        g_bias[1][t] = s2;
    }
}

// ---------------- smem layout (bytes) ----------------------------------------
// fp16 tiles: 128 x STRIDE = 18432 B each; weights: 64 x STRIDE fp16 = 9216 B
static constexpr int OFF_X1HI = 0;
static constexpr int OFF_X1LO = 18432;
static constexpr int OFF_X2HI = 36864;
static constexpr int OFF_X2LO = 55296;
static constexpr int OFF_M1   = 73728;
static constexpr int OFF_M2   = 82944;
static constexpr int OFF_B1   = 92160;
static constexpr int OFF_B2   = 92416;
static constexpr int OFF_G1   = 92672;
static constexpr int OFF_BE1  = 92928;
static constexpr int OFF_G2   = 93184;
static constexpr int OFF_BE2  = 93440;
static constexpr int SMEM_TOTAL = 93696;

__device__ __forceinline__ void mma16816(float* d, const uint32_t* a, const uint32_t* b) {
    asm volatile(
        "mma.sync.aligned.m16n8k16.row.col.f32.f16.f16.f32 "
        "{%0,%1,%2,%3}, {%4,%5,%6,%7}, {%8,%9}, {%0,%1,%2,%3};"
        : "+f"(d[0]), "+f"(d[1]), "+f"(d[2]), "+f"(d[3])
        : "r"(a[0]), "r"(a[1]), "r"(a[2]), "r"(a[3]), "r"(b[0]), "r"(b[1]));
}

__global__ void __launch_bounds__(256, 2)
fused_kernel(const float* __restrict__ v1, const float* __restrict__ v2,
             const float* __restrict__ g1, const float* __restrict__ be1,
             const float* __restrict__ g2, const float* __restrict__ be2,
             float* __restrict__ out, int Btot) {
    extern __shared__ char smem[];
    const int tid = threadIdx.x;
    const size_t row0 = (size_t)blockIdx.x * TILE_M;

    // --- load v1/v2 tiles (coalesced f32x4), split fp16 hi/lo into smem ---
#pragma unroll
    for (int pass = 0; pass < 2; pass++) {
        const float* src = pass ? v2 : v1;
        __half* dhi = (__half*)(smem + (pass ? OFF_X2HI : OFF_X1HI));
        __half* dlo = (__half*)(smem + (pass ? OFF_X2LO : OFF_X1LO));
        for (int i = tid; i < 2048; i += 256) {
            int r = i >> 4, c4 = i & 15;
            float4 f = *(const float4*)(src + (row0 + r) * EMBED + c4 * 4);
            __half2 h0 = __floats2half2_rn(f.x, f.y);
            __half2 h1 = __floats2half2_rn(f.z, f.w);
            float2 e0 = __half22float2(h0), e1 = __half22float2(h1);
            __half2 l0 = __floats2half2_rn(f.x - e0.x, f.y - e0.y);
            __half2 l1 = __floats2half2_rn(f.z - e1.x, f.w - e1.y);
            *(uint2*)(dhi + r * STRIDE + c4 * 4) =
                make_uint2(*(uint32_t*)&h0, *(uint32_t*)&h1);
            *(uint2*)(dlo + r * STRIDE + c4 * 4) =
                make_uint2(*(uint32_t*)&l0, *(uint32_t*)&l1);
        }
    }

    // --- weights into padded smem ---
#pragma unroll
    for (int m = 0; m < 2; m++) {
        uint32_t* dst = (uint32_t*)(smem + (m ? OFF_M2 : OFF_M1));
        const uint32_t* srcw = (const uint32_t*)g_M[m];
        for (int i = tid; i < 2048; i += 256) {
            int j = i >> 5, k2 = i & 31;  // row j, 32 b32 per 64-half row
            dst[j * (STRIDE / 2) + k2] = srcw[i];
        }
    }

    // --- constants ---
    if (tid < 64) {
        ((float*)(smem + OFF_B1))[tid]  = g_bias[0][tid];
        ((float*)(smem + OFF_B2))[tid]  = g_bias[1][tid];
        ((float*)(smem + OFF_G1))[tid]  = g1[tid];
        ((float*)(smem + OFF_BE1))[tid] = be1[tid];
        ((float*)(smem + OFF_G2))[tid]  = g2[tid];
        ((float*)(smem + OFF_BE2))[tid] = be2[tid];
    }
    __syncthreads();

    const int wid = tid >> 5, lane = tid & 31;
    const int g = lane >> 2, tq = lane & 3;
    const int wrow = wid * 16;  // warp's row base within tile

#pragma unroll
    for (int o = 0; o < 2; o++) {
        // out1 (o=0): A = v2, residual = v1; out2 (o=1): A = v1, residual = v2
        const __half* A  = (const __half*)(smem + (o ? OFF_X1HI : OFF_X2HI));
        const __half* RH = (const __half*)(smem + (o ? OFF_X2HI : OFF_X1HI));
        const __half* RL = (const __half*)(smem + (o ? OFF_X2LO : OFF_X1LO));
        const __half* M  = (const __half*)(smem + (o ? OFF_M2 : OFF_M1));
        const float* Cb  = (const float*)(smem + (o ? OFF_B2 : OFF_B1));
        const float* Gm  = (const float*)(smem + (o ? OFF_G2 : OFF_G1));
        const float* Bt  = (const float*)(smem + (o ? OFF_BE2 : OFF_BE1));
        float* outp = out + (o ? (size_t)Btot * EMBED : 0) + (row0 + wrow) * EMBED;

        // A fragments: rows wrow+g(+8), k-tiles 0..3
        uint32_t a[4][4];
#pragma unroll
        for (int kt = 0; kt < 4; kt++) {
            const __half* base = A + (wrow + g) * STRIDE + kt * 16 + tq * 2;
            a[kt][0] = *(const uint32_t*)(base);
            a[kt][1] = *(const uint32_t*)(base + 8 * STRIDE);
            a[kt][2] = *(const uint32_t*)(base + 8);
            a[kt][3] = *(const uint32_t*)(base + 8 * STRIDE + 8);
        }

        float acc[8][4];
#pragma unroll
        for (int nt = 0; nt < 8; nt++)
#pragma unroll
            for (int q = 0; q < 4; q++) acc[nt][q] = 0.f;

#pragma unroll
        for (int nt = 0; nt < 8; nt++) {
#pragma unroll
            for (int kt = 0; kt < 4; kt++) {
                const __half* bb = M + (nt * 8 + g) * STRIDE + kt * 16 + tq * 2;
                uint32_t b[2];
                b[0] = *(const uint32_t*)bb;
                b[1] = *(const uint32_t*)(bb + 8);
                mma16816(acc[nt], a[kt], b);
            }
        }

        // --- epilogue: bias + residual(hi+lo) + LayerNorm ---
        float x0[16], x1[16];
        float s0 = 0.f, ss0 = 0.f, s1 = 0.f, ss1 = 0.f;
#pragma unroll
        for (int nt = 0; nt < 8; nt++) {
            int col = nt * 8 + tq * 2;
            float2 cb = *(const float2*)(Cb + col);
            const __half* rh0 = RH + (wrow + g) * STRIDE + col;
            const __half* rl0 = RL + (wrow + g) * STRIDE + col;
            float2 r0h = __half22float2(*(const __half2*)rh0);
            float2 r0l = __half22float2(*(const __half2*)rl0);
            float2 r1h = __half22float2(*(const __half2*)(rh0 + 8 * STRIDE));
            float2 r1l = __half22float2(*(const __half2*)(rl0 + 8 * STRIDE));
            float e00 = acc[nt][0] + cb.x + (r0h.x + r0l.x);
            float e01 = acc[nt][1] + cb.y + (r0h.y + r0l.y);
            float e10 = acc[nt][2] + cb.x + (r1h.x + r1l.x);
            float e11 = acc[nt][3] + cb.y + (r1h.y + r1l.y);
            x0[nt * 2] = e00; x0[nt * 2 + 1] = e01;
            x1[nt * 2] = e10; x1[nt * 2 + 1] = e11;
            s0 += e00 + e01; ss0 += e00 * e00 + e01 * e01;
            s1 += e10 + e11; ss1 += e10 * e10 + e11 * e11;
        }
        s0  += __shfl_xor_sync(0xFFFFFFFFu, s0, 1);
        s0  += __shfl_xor_sync(0xFFFFFFFFu, s0, 2);
        ss0 += __shfl_xor_sync(0xFFFFFFFFu, ss0, 1);
        ss0 += __shfl_xor_sync(0xFFFFFFFFu, ss0, 2);
        s1  += __shfl_xor_sync(0xFFFFFFFFu, s1, 1);
        s1  += __shfl_xor_sync(0xFFFFFFFFu, s1, 2);
        ss1 += __shfl_xor_sync(0xFFFFFFFFu, ss1, 1);
        ss1 += __shfl_xor_sync(0xFFFFFFFFu, ss1, 2);
        float mu0 = s0 * (1.f / 64.f);
        float mu1 = s1 * (1.f / 64.f);
        float rs0 = rsqrtf(ss0 * (1.f / 64.f) - mu0 * mu0 + 1e-5f);
        float rs1 = rsqrtf(ss1 * (1.f / 64.f) - mu1 * mu1 + 1e-5f);

#pragma unroll
        for (int nt = 0; nt < 8; nt++) {
            int col = nt * 8 + tq * 2;
            float2 gm = *(const float2*)(Gm + col);
            float2 bt = *(const float2*)(Bt + col);
            float2 o0, o1;
            o0.x = (x0[nt * 2]     - mu0) * rs0 * gm.x + bt.x;
            o0.y = (x0[nt * 2 + 1] - mu0) * rs0 * gm.y + bt.y;
            o1.x = (x1[nt * 2]     - mu1) * rs1 * gm.x + bt.x;
            o1.y = (x1[nt * 2 + 1] - mu1) * rs1 * gm.y + bt.y;
            *(float2*)(outp + (size_t)g * EMBED + col) = o0;
            *(float2*)(outp + (size_t)(g + 8) * EMBED + col) = o1;
        }
        // no cross-warp smem hazard between the two outputs: tiles are read-only
    }
}

// ---------------- launcher ---------------------------------------------------
extern "C" void kernel_launch(void* const* d_in, const int* in_sizes, int n_in,
                              void* d_out, int out_size) {
    // metadata order:
    // 0 v1, 1 v2, 2 Wq1, 3 bq1, 4 Wk2, 5 bk2, 6 Wv2, 7 bv2, 8 Wo1, 9 bo1,
    // 10 Wq2, 11 bq2, 12 Wk1, 13 bk1, 14 Wv1, 15 bv1, 16 Wo2, 17 bo2,
    // 18 g1, 19 be1, 20 g2, 21 be2
    const float* v1  = (const float*)d_in[0];
    const float* v2  = (const float*)d_in[1];
    const float* Wv2 = (const float*)d_in[6];
    const float* bv2 = (const float*)d_in[7];
    const float* Wo1 = (const float*)d_in[8];
    const float* bo1 = (const float*)d_in[9];
    const float* Wv1 = (const float*)d_in[14];
    const float* bv1 = (const float*)d_in[15];
    const float* Wo2 = (const float*)d_in[16];
    const float* bo2 = (const float*)d_in[17];
    const float* g1  = (const float*)d_in[18];
    const float* be1 = (const float*)d_in[19];
    const float* g2  = (const float*)d_in[20];
    const float* be2 = (const float*)d_in[21];
    float* out = (float*)d_out;

    int Btot = in_sizes[0] / EMBED;

    prep_kernel<<<1, 1024>>>(Wo1, Wv2, bv2, bo1, Wo2, Wv1, bv1, bo2);

    cudaFuncSetAttribute(fused_kernel,
                         cudaFuncAttributeMaxDynamicSharedMemorySize, SMEM_TOTAL);
    fused_kernel<<<Btot / TILE_M, 256, SMEM_TOTAL>>>(v1, v2, g1, be1, g2, be2,
                                                     out, Btot);
}

// round 3
// speedup vs baseline: 1.4414x; 1.4414x over previous
#include <cuda_runtime.h>
#include <cuda_fp16.h>
#include <cstdint>

// ============================================================================
// Reduction: softmax over length-1 key axis == 1  =>  attended = V-projection.
//   a1 = LN( v2 @ (Wo1@Wv2)^T + (Wo1@bv2 + bo1) + v1 ; g1, be1 )
//   a2 = LN( v1 @ (Wo2@Wv1)^T + (Wo2@bv1 + bo2) + v2 ; g2, be2 )
// GEMMs via mma.sync fp16 (single pass). Inputs loaded ONCE, directly in MMA
// fragment layout (fully sector-coalesced), kept in f32 regs for an exact
// residual; converted in-register to fp16 for the A operand. No input smem.
// ============================================================================

#define EMBED 64
#define TILE_M 128
#define STRIDE 72  // fp16 elems per smem row for weights (conflict-free)

// ---------------- device scratch for folded weights -------------------------
__device__ __half g_M[2][EMBED * EMBED];   // [j][k] row-major, fp16
__device__ float  g_bias[2][EMBED];

// ---------------- prep: fold Wo@Wv -> fp16, Wo@bv + bo -> f32 ---------------
__global__ void prep_kernel(const float* __restrict__ Wo1, const float* __restrict__ Wv2,
                            const float* __restrict__ bv2, const float* __restrict__ bo1,
                            const float* __restrict__ Wo2, const float* __restrict__ Wv1,
                            const float* __restrict__ bv1, const float* __restrict__ bo2) {
    int idx = blockIdx.x * 256 + threadIdx.x;   // 16 blocks x 256 = 4096
    int j = idx >> 6, k = idx & 63;
    float s1 = 0.f, s2 = 0.f;
#pragma unroll 8
    for (int i = 0; i < EMBED; i++) {
        s1 = fmaf(Wo1[j * 64 + i], Wv2[i * 64 + k], s1);
        s2 = fmaf(Wo2[j * 64 + i], Wv1[i * 64 + k], s2);
    }
    g_M[0][idx] = __float2half_rn(s1);
    g_M[1][idx] = __float2half_rn(s2);
    if (blockIdx.x == 0 && threadIdx.x < EMBED) {
        int t = threadIdx.x;
        float b1 = bo1[t], b2 = bo2[t];
#pragma unroll 8
        for (int i = 0; i < EMBED; i++) {
            b1 = fmaf(Wo1[t * 64 + i], bv2[i], b1);
            b2 = fmaf(Wo2[t * 64 + i], bv1[i], b2);
        }
        g_bias[0][t] = b1;
        g_bias[1][t] = b2;
    }
}

__device__ __forceinline__ void mma16816(float* d, const uint32_t* a, const uint32_t* b) {
    asm volatile(
        "mma.sync.aligned.m16n8k16.row.col.f32.f16.f16.f32 "
        "{%0,%1,%2,%3}, {%4,%5,%6,%7}, {%8,%9}, {%0,%1,%2,%3};"
        : "+f"(d[0]), "+f"(d[1]), "+f"(d[2]), "+f"(d[3])
        : "r"(a[0]), "r"(a[1]), "r"(a[2]), "r"(a[3]), "r"(b[0]), "r"(b[1]));
}

__device__ __forceinline__ float2 ldcs_f2(const float* p) {
    float2 r;
    asm volatile("ld.global.cs.v2.f32 {%0,%1}, [%2];"
                 : "=f"(r.x), "=f"(r.y) : "l"(p));
    return r;
}
__device__ __forceinline__ void stcs_f2(float* p, float2 v) {
    asm volatile("st.global.cs.v2.f32 [%0], {%1,%2};"
                 :: "l"(p), "f"(v.x), "f"(v.y) : "memory");
}

// smem: two weight matrices (padded) + constants
struct SmemLayout {
    __half M[2][EMBED * STRIDE];
    float  cb[2][EMBED];
    float  gm[2][EMBED];
    float  bt[2][EMBED];
};

__global__ void __launch_bounds__(256, 2)
fused_kernel(const float* __restrict__ v1, const float* __restrict__ v2,
             const float* __restrict__ g1, const float* __restrict__ be1,
             const float* __restrict__ g2, const float* __restrict__ be2,
             float* __restrict__ out, int Btot) {
    __shared__ SmemLayout sm;
    const int tid = threadIdx.x;
    const int wid = tid >> 5, lane = tid & 31;
    const int g = lane >> 2, tq = lane & 3;
    const int wrow = wid * 16;
    const size_t row0 = (size_t)blockIdx.x * TILE_M;

    // --- load input fragments directly from global (each byte read once) ---
    // frag idx = kt*4 + p: p0=(row g,   col kt*16+tq*2)
    //                      p1=(row g+8, col kt*16+tq*2)
    //                      p2=(row g,   col kt*16+tq*2+8)
    //                      p3=(row g+8, col kt*16+tq*2+8)
    float2 v1f[16], v2f[16];
    {
        const float* b1 = v1 + (row0 + wrow + g) * EMBED + tq * 2;
        const float* b2 = v2 + (row0 + wrow + g) * EMBED + tq * 2;
#pragma unroll
        for (int kt = 0; kt < 4; kt++) {
            int c0 = kt * 16, c8 = kt * 16 + 8;
            v1f[kt * 4 + 0] = ldcs_f2(b1 + c0);
            v1f[kt * 4 + 1] = ldcs_f2(b1 + 8 * EMBED + c0);
            v1f[kt * 4 + 2] = ldcs_f2(b1 + c8);
            v1f[kt * 4 + 3] = ldcs_f2(b1 + 8 * EMBED + c8);
            v2f[kt * 4 + 0] = ldcs_f2(b2 + c0);
            v2f[kt * 4 + 1] = ldcs_f2(b2 + 8 * EMBED + c0);
            v2f[kt * 4 + 2] = ldcs_f2(b2 + c8);
            v2f[kt * 4 + 3] = ldcs_f2(b2 + 8 * EMBED + c8);
        }
    }

    // --- weights into padded smem (L2-resident after first wave) ---
#pragma unroll
    for (int m = 0; m < 2; m++) {
        uint32_t* dst = (uint32_t*)sm.M[m];
        const uint32_t* srcw = (const uint32_t*)g_M[m];
        for (int i = tid; i < 2048; i += 256) {
            int j = i >> 5, k2 = i & 31;
            dst[j * (STRIDE / 2) + k2] = srcw[i];
        }
    }
    if (tid < 64) {
        sm.cb[0][tid] = g_bias[0][tid];
        sm.cb[1][tid] = g_bias[1][tid];
        sm.gm[0][tid] = g1[tid];
        sm.gm[1][tid] = g2[tid];
        sm.bt[0][tid] = be1[tid];
        sm.bt[1][tid] = be2[tid];
    }
    __syncthreads();

#pragma unroll
    for (int o = 0; o < 2; o++) {
        // o=0: A = v2 frags, residual = v1; o=1: A = v1 frags, residual = v2
        const float2* Af  = o ? v1f : v2f;
        const float2* Rf  = o ? v2f : v1f;
        const __half* M   = sm.M[o];
        const float*  Cb  = sm.cb[o];
        const float*  Gm  = sm.gm[o];
        const float*  Bt  = sm.bt[o];
        float* outp = out + (o ? (size_t)Btot * EMBED : 0) + (row0 + wrow) * EMBED;

        float acc[8][4];
#pragma unroll
        for (int nt = 0; nt < 8; nt++)
#pragma unroll
            for (int q = 0; q < 4; q++) acc[nt][q] = 0.f;

#pragma unroll
        for (int kt = 0; kt < 4; kt++) {
            uint32_t a[4];
#pragma unroll
            for (int p = 0; p < 4; p++) {
                float2 f = Af[kt * 4 + p];
                __half2 h = __floats2half2_rn(f.x, f.y);
                a[p] = *reinterpret_cast<uint32_t*>(&h);
            }
#pragma unroll
            for (int nt = 0; nt < 8; nt++) {
                const __half* bb = M + (nt * 8 + g) * STRIDE + kt * 16 + tq * 2;
                uint32_t b[2];
                b[0] = *(const uint32_t*)bb;
                b[1] = *(const uint32_t*)(bb + 8);
                mma16816(acc[nt], a, b);
            }
        }

        // --- epilogue: bias + exact f32 residual + LayerNorm (recompute) ---
        float s0 = 0.f, ss0 = 0.f, s1 = 0.f, ss1 = 0.f;
#pragma unroll
        for (int nt = 0; nt < 8; nt++) {
            int fi = (nt >> 1) * 4 + (nt & 1) * 2;
            float2 cb = *(const float2*)(Cb + nt * 8 + tq * 2);
            float2 r0 = Rf[fi], r1 = Rf[fi + 1];
            float e00 = acc[nt][0] + cb.x + r0.x;
            float e01 = acc[nt][1] + cb.y + r0.y;
            float e10 = acc[nt][2] + cb.x + r1.x;
            float e11 = acc[nt][3] + cb.y + r1.y;
            s0 += e00 + e01; ss0 += e00 * e00 + e01 * e01;
            s1 += e10 + e11; ss1 += e10 * e10 + e11 * e11;
        }
        s0  += __shfl_xor_sync(0xFFFFFFFFu, s0, 1);
        s0  += __shfl_xor_sync(0xFFFFFFFFu, s0, 2);
        ss0 += __shfl_xor_sync(0xFFFFFFFFu, ss0, 1);
        ss0 += __shfl_xor_sync(0xFFFFFFFFu, ss0, 2);
        s1  += __shfl_xor_sync(0xFFFFFFFFu, s1, 1);
        s1  += __shfl_xor_sync(0xFFFFFFFFu, s1, 2);
        ss1 += __shfl_xor_sync(0xFFFFFFFFu, ss1, 1);
        ss1 += __shfl_xor_sync(0xFFFFFFFFu, ss1, 2);
        float mu0 = s0 * (1.f / 64.f);
        float mu1 = s1 * (1.f / 64.f);
        float rs0 = rsqrtf(ss0 * (1.f / 64.f) - mu0 * mu0 + 1e-5f);
        float rs1 = rsqrtf(ss1 * (1.f / 64.f) - mu1 * mu1 + 1e-5f);

#pragma unroll
        for (int nt = 0; nt < 8; nt++) {
            int fi = (nt >> 1) * 4 + (nt & 1) * 2;
            int col = nt * 8 + tq * 2;
            float2 cb = *(const float2*)(Cb + col);
            float2 gm = *(const float2*)(Gm + col);
            float2 bt = *(const float2*)(Bt + col);
            float2 r0 = Rf[fi], r1 = Rf[fi + 1];
            float2 o0, o1;
            o0.x = (acc[nt][0] + cb.x + r0.x - mu0) * rs0 * gm.x + bt.x;
            o0.y = (acc[nt][1] + cb.y + r0.y - mu0) * rs0 * gm.y + bt.y;
            o1.x = (acc[nt][2] + cb.x + r1.x - mu1) * rs1 * gm.x + bt.x;
            o1.y = (acc[nt][3] + cb.y + r1.y - mu1) * rs1 * gm.y + bt.y;
            stcs_f2(outp + (size_t)g * EMBED + col, o0);
            stcs_f2(outp + (size_t)(g + 8) * EMBED + col, o1);
        }
    }
}

// ---------------- launcher ---------------------------------------------------
extern "C" void kernel_launch(void* const* d_in, const int* in_sizes, int n_in,
                              void* d_out, int out_size) {
    // 0 v1, 1 v2, 2 Wq1, 3 bq1, 4 Wk2, 5 bk2, 6 Wv2, 7 bv2, 8 Wo1, 9 bo1,
    // 10 Wq2, 11 bq2, 12 Wk1, 13 bk1, 14 Wv1, 15 bv1, 16 Wo2, 17 bo2,
    // 18 g1, 19 be1, 20 g2, 21 be2
    const float* v1  = (const float*)d_in[0];
    const float* v2  = (const float*)d_in[1];
    const float* Wv2 = (const float*)d_in[6];
    const float* bv2 = (const float*)d_in[7];
    const float* Wo1 = (const float*)d_in[8];
    const float* bo1 = (const float*)d_in[9];
    const float* Wv1 = (const float*)d_in[14];
    const float* bv1 = (const float*)d_in[15];
    const float* Wo2 = (const float*)d_in[16];
    const float* bo2 = (const float*)d_in[17];
    const float* g1  = (const float*)d_in[18];
    const float* be1 = (const float*)d_in[19];
    const float* g2  = (const float*)d_in[20];
    const float* be2 = (const float*)d_in[21];
    float* out = (float*)d_out;

    int Btot = in_sizes[0] / EMBED;

    prep_kernel<<<16, 256>>>(Wo1, Wv2, bv2, bo1, Wo2, Wv1, bv1, bo2);
    fused_kernel<<<Btot / TILE_M, 256>>>(v1, v2, g1, be1, g2, be2, out, Btot);
}

// round 4
// speedup vs baseline: 1.6653x; 1.1554x over previous
#include <cuda_runtime.h>
#include <cuda_fp16.h>
#include <cstdint>

// ============================================================================
// Reduction: softmax over length-1 key axis == 1  =>  attended = V-projection.
//   a1 = LN( v2 @ (Wo1@Wv2)^T + (Wo1@bv2 + bo1) + v1 ; g1, be1 )
//   a2 = LN( v1 @ (Wo2@Wv1)^T + (Wo2@bv1 + bo2) + v2 ; g2, be2 )
//
// Column-permutation trick: GEMM is invariant under permuting k (applied to
// both A cols and M cols) and n (applied to M rows + bias/gamma/beta + output
// placement); LayerNorm stats are permutation-invariant. Choose
//   P(l): bits {b1 b0 | h | t1 t0 | j} -> {b1 b0 | t1 t0 | h | j}
// so that every lane's MMA A-fragments, residual values and outputs are
// CONTIGUOUS float4s. => all global access is LDG.128/STG.128, A-frags are
// direct register packs, residual is exact f32 from the same registers.
// B fragments come from smem via ldmatrix.x4 (M stored pre-permuted by prep).
// ============================================================================

#define EMBED 64
#define TILE_M 128
#define STRIDE 72  // halves per smem row of M (144B: conflict-free ldmatrix)

__device__ __host__ __forceinline__ int permP(int l) {
    return (l & 48) | ((l & 6) << 1) | ((l & 8) >> 2) | (l & 1);
}

// ---------------- device scratch for folded weights -------------------------
__device__ __half g_Mp[2][EMBED * EMBED];  // [n_l][k_l], both dims P-permuted
__device__ float  g_bias[2][EMBED];        // physical order

// ---------------- prep: fold Wo@Wv -> permuted fp16, Wo@bv + bo -> f32 ------
__global__ void prep_kernel(const float* __restrict__ Wo1, const float* __restrict__ Wv2,
                            const float* __restrict__ bv2, const float* __restrict__ bo1,
                            const float* __restrict__ Wo2, const float* __restrict__ Wv1,
                            const float* __restrict__ bv1, const float* __restrict__ bo2) {
    if (blockIdx.x == 16) {
        int t = threadIdx.x;
        if (t < EMBED) {
            float b1 = bo1[t], b2 = bo2[t];
#pragma unroll 16
            for (int i = 0; i < EMBED; i++) {
                b1 = fmaf(Wo1[t * 64 + i], bv2[i], b1);
                b2 = fmaf(Wo2[t * 64 + i], bv1[i], b2);
            }
            g_bias[0][t] = b1;
            g_bias[1][t] = b2;
        }
        return;
    }
    int idx = blockIdx.x * 256 + threadIdx.x;  // 4096 elements
    int jp = permP(idx >> 6), kp = permP(idx & 63);
    float s1 = 0.f, s2 = 0.f;
#pragma unroll 16
    for (int i = 0; i < EMBED; i++) {
        s1 = fmaf(Wo1[jp * 64 + i], Wv2[i * 64 + kp], s1);
        s2 = fmaf(Wo2[jp * 64 + i], Wv1[i * 64 + kp], s2);
    }
    g_Mp[0][idx] = __float2half_rn(s1);
    g_Mp[1][idx] = __float2half_rn(s2);
}

// ---------------- asm helpers ------------------------------------------------
__device__ __forceinline__ void mma16816(float* d, const uint32_t* a, const uint32_t* b) {
    asm volatile(
        "mma.sync.aligned.m16n8k16.row.col.f32.f16.f16.f32 "
        "{%0,%1,%2,%3}, {%4,%5,%6,%7}, {%8,%9}, {%0,%1,%2,%3};"
        : "+f"(d[0]), "+f"(d[1]), "+f"(d[2]), "+f"(d[3])
        : "r"(a[0]), "r"(a[1]), "r"(a[2]), "r"(a[3]), "r"(b[0]), "r"(b[1]));
}
__device__ __forceinline__ float4 ldcs_f4(const float* p) {
    float4 r;
    asm volatile("ld.global.cs.v4.f32 {%0,%1,%2,%3}, [%4];"
                 : "=f"(r.x), "=f"(r.y), "=f"(r.z), "=f"(r.w) : "l"(p));
    return r;
}
__device__ __forceinline__ void stcs_f4(float* p, float4 v) {
    asm volatile("st.global.cs.v4.f32 [%0], {%1,%2,%3,%4};"
                 :: "l"(p), "f"(v.x), "f"(v.y), "f"(v.z), "f"(v.w) : "memory");
}
__device__ __forceinline__ uint32_t smem_u32(const void* p) {
    uint32_t a;
    asm("{ .reg .u64 t; cvta.to.shared.u64 t, %1; cvt.u32.u64 %0, t; }"
        : "=r"(a) : "l"(p));
    return a;
}
__device__ __forceinline__ void ldmatrix_x4(uint32_t* b, uint32_t addr) {
    asm volatile("ldmatrix.sync.aligned.m8n8.x4.shared.b16 {%0,%1,%2,%3}, [%4];"
                 : "=r"(b[0]), "=r"(b[1]), "=r"(b[2]), "=r"(b[3]) : "r"(addr));
}
__device__ __forceinline__ uint32_t packh2(float a, float b) {
    __half2 h = __floats2half2_rn(a, b);
    return *reinterpret_cast<uint32_t*>(&h);
}

struct SmemLayout {
    __half M[2][EMBED * STRIDE];  // P-permuted folded weights
    float  cb[2][EMBED];          // physical order
    float  gm[2][EMBED];
    float  bt[2][EMBED];
};

__global__ void __launch_bounds__(256, 2)
fused_kernel(const float* __restrict__ v1, const float* __restrict__ v2,
             const float* __restrict__ g1, const float* __restrict__ be1,
             const float* __restrict__ g2, const float* __restrict__ be2,
             float* __restrict__ out, int Btot) {
    __shared__ SmemLayout sm;
    const int tid = threadIdx.x;
    const int wid = tid >> 5, lane = tid & 31;
    const int g = lane >> 2, tq = lane & 3;
    const int wrow = wid * 16;
    const size_t row0 = (size_t)blockIdx.x * TILE_M;

    // --- inputs: 8 LDG.128 per tensor per thread; each float4 is:
    //     (row wrow+g (+8), physical cols 16kt+4tq .. +3)
    // These registers serve (a) A-fragments (k P-permuted), (b) exact f32
    // residual, (c) the output store positions. Each byte read once.
    float4 v1q[4][2], v2q[4][2];
    {
        const float* b1 = v1 + (row0 + wrow + g) * EMBED + tq * 4;
        const float* b2 = v2 + (row0 + wrow + g) * EMBED + tq * 4;
#pragma unroll
        for (int kt = 0; kt < 4; kt++) {
            v1q[kt][0] = ldcs_f4(b1 + kt * 16);
            v1q[kt][1] = ldcs_f4(b1 + 8 * EMBED + kt * 16);
            v2q[kt][0] = ldcs_f4(b2 + kt * 16);
            v2q[kt][1] = ldcs_f4(b2 + 8 * EMBED + kt * 16);
        }
    }

    // --- permuted weights into padded smem ---
#pragma unroll
    for (int m = 0; m < 2; m++) {
        uint32_t* dst = (uint32_t*)sm.M[m];
        const uint32_t* srcw = (const uint32_t*)g_Mp[m];
        for (int i = tid; i < 2048; i += 256) {
            int j = i >> 5, k2 = i & 31;
            dst[j * (STRIDE / 2) + k2] = srcw[i];
        }
    }
    if (tid < 64) {
        sm.cb[0][tid] = g_bias[0][tid];
        sm.cb[1][tid] = g_bias[1][tid];
        sm.gm[0][tid] = g1[tid];
        sm.gm[1][tid] = g2[tid];
        sm.bt[0][tid] = be1[tid];
        sm.bt[1][tid] = be2[tid];
    }
    __syncthreads();

    const uint32_t smM0 = smem_u32(sm.M[0]);
    // ldmatrix lane offset: lanes 0-7 -> (kt=2ktp, k+0), 8-15 -> (kt, k+8),
    // 16-23 -> (kt+1, k+0), 24-31 -> (kt+1, k+8); bytes.
    const uint32_t lmoff = (uint32_t)((lane & 7) * (STRIDE * 2) +
                                      ((lane >> 4) & 1) * 32 +
                                      ((lane >> 3) & 1) * 16);

#pragma unroll
    for (int o = 0; o < 2; o++) {
        // o=0: A = v2 (GEMM), residual = v1 ; o=1: swapped.
        const float4 (*Af)[2] = o ? v1q : v2q;
        const float4 (*Rf)[2] = o ? v2q : v1q;
        const uint32_t smM = smM0 + (uint32_t)o * (EMBED * STRIDE * 2);

        float acc[8][4];
#pragma unroll
        for (int nt = 0; nt < 8; nt++)
#pragma unroll
            for (int q = 0; q < 4; q++) acc[nt][q] = 0.f;

#pragma unroll
        for (int ktp = 0; ktp < 2; ktp++) {
            // A fragments for kt = 2*ktp and 2*ktp+1: direct packs.
            uint32_t aA[2][4];
#pragma unroll
            for (int s = 0; s < 2; s++) {
                const float4 f0 = Af[2 * ktp + s][0];
                const float4 f1 = Af[2 * ktp + s][1];
                aA[s][0] = packh2(f0.x, f0.y);
                aA[s][1] = packh2(f1.x, f1.y);
                aA[s][2] = packh2(f0.z, f0.w);
                aA[s][3] = packh2(f1.z, f1.w);
            }
#pragma unroll
            for (int nt = 0; nt < 8; nt++) {
                uint32_t b[4];
                ldmatrix_x4(b, smM + lmoff + (uint32_t)(nt * 8 * STRIDE * 2 + ktp * 64));
                mma16816(acc[nt], aA[0], b);
                mma16816(acc[nt], aA[1], b + 2);
            }
        }

        // --- epilogue: bias + exact residual folded into acc, then LN ---
        const float4* cb4 = (const float4*)sm.cb[o];
        float s0 = 0.f, ss0 = 0.f, s1 = 0.f, ss1 = 0.f;
#pragma unroll
        for (int kt = 0; kt < 4; kt++) {
            float4 c = cb4[kt * 4 + tq];
            float4 r0 = Rf[kt][0], r1 = Rf[kt][1];
            acc[2 * kt][0] += c.x + r0.x;
            acc[2 * kt][1] += c.y + r0.y;
            acc[2 * kt + 1][0] += c.z + r0.z;
            acc[2 * kt + 1][1] += c.w + r0.w;
            acc[2 * kt][2] += c.x + r1.x;
            acc[2 * kt][3] += c.y + r1.y;
            acc[2 * kt + 1][2] += c.z + r1.z;
            acc[2 * kt + 1][3] += c.w + r1.w;
            s0 += acc[2 * kt][0] + acc[2 * kt][1] + acc[2 * kt + 1][0] + acc[2 * kt + 1][1];
            ss0 += acc[2 * kt][0] * acc[2 * kt][0] + acc[2 * kt][1] * acc[2 * kt][1] +
                   acc[2 * kt + 1][0] * acc[2 * kt + 1][0] + acc[2 * kt + 1][1] * acc[2 * kt + 1][1];
            s1 += acc[2 * kt][2] + acc[2 * kt][3] + acc[2 * kt + 1][2] + acc[2 * kt + 1][3];
            ss1 += acc[2 * kt][2] * acc[2 * kt][2] + acc[2 * kt][3] * acc[2 * kt][3] +
                   acc[2 * kt + 1][2] * acc[2 * kt + 1][2] + acc[2 * kt + 1][3] * acc[2 * kt + 1][3];
        }
        s0  += __shfl_xor_sync(0xFFFFFFFFu, s0, 1);
        s0  += __shfl_xor_sync(0xFFFFFFFFu, s0, 2);
        ss0 += __shfl_xor_sync(0xFFFFFFFFu, ss0, 1);
        ss0 += __shfl_xor_sync(0xFFFFFFFFu, ss0, 2);
        s1  += __shfl_xor_sync(0xFFFFFFFFu, s1, 1);
        s1  += __shfl_xor_sync(0xFFFFFFFFu, s1, 2);
        ss1 += __shfl_xor_sync(0xFFFFFFFFu, ss1, 1);
        ss1 += __shfl_xor_sync(0xFFFFFFFFu, ss1, 2);
        float mu0 = s0 * (1.f / 64.f);
        float mu1 = s1 * (1.f / 64.f);
        float rs0 = rsqrtf(ss0 * (1.f / 64.f) - mu0 * mu0 + 1e-5f);
        float rs1 = rsqrtf(ss1 * (1.f / 64.f) - mu1 * mu1 + 1e-5f);

        const float4* gm4 = (const float4*)sm.gm[o];
        const float4* bt4 = (const float4*)sm.bt[o];
        float* outp = out + (o ? (size_t)Btot * EMBED : 0) +
                      (row0 + wrow + g) * EMBED + tq * 4;
#pragma unroll
        for (int kt = 0; kt < 4; kt++) {
            float4 G = gm4[kt * 4 + tq], T = bt4[kt * 4 + tq];
            float4 y0, y1;
            y0.x = (acc[2 * kt][0] - mu0) * rs0 * G.x + T.x;
            y0.y = (acc[2 * kt][1] - mu0) * rs0 * G.y + T.y;
            y0.z = (acc[2 * kt + 1][0] - mu0) * rs0 * G.z + T.z;
            y0.w = (acc[2 * kt + 1][1] - mu0) * rs0 * G.w + T.w;
            y1.x = (acc[2 * kt][2] - mu1) * rs1 * G.x + T.x;
            y1.y = (acc[2 * kt][3] - mu1) * rs1 * G.y + T.y;
            y1.z = (acc[2 * kt + 1][2] - mu1) * rs1 * G.z + T.z;
            y1.w = (acc[2 * kt + 1][3] - mu1) * rs1 * G.w + T.w;
            stcs_f4(outp + kt * 16, y0);
            stcs_f4(outp + 8 * EMBED + kt * 16, y1);
        }
    }
}

// ---------------- launcher ---------------------------------------------------
extern "C" void kernel_launch(void* const* d_in, const int* in_sizes, int n_in,
                              void* d_out, int out_size) {
    // 0 v1, 1 v2, 2 Wq1, 3 bq1, 4 Wk2, 5 bk2, 6 Wv2, 7 bv2, 8 Wo1, 9 bo1,
    // 10 Wq2, 11 bq2, 12 Wk1, 13 bk1, 14 Wv1, 15 bv1, 16 Wo2, 17 bo2,
    // 18 g1, 19 be1, 20 g2, 21 be2
    const float* v1  = (const float*)d_in[0];
    const float* v2  = (const float*)d_in[1];
    const float* Wv2 = (const float*)d_in[6];
    const float* bv2 = (const float*)d_in[7];
    const float* Wo1 = (const float*)d_in[8];
    const float* bo1 = (const float*)d_in[9];
    const float* Wv1 = (const float*)d_in[14];
    const float* bv1 = (const float*)d_in[15];
    const float* Wo2 = (const float*)d_in[16];
    const float* bo2 = (const float*)d_in[17];
    const float* g1  = (const float*)d_in[18];
    const float* be1 = (const float*)d_in[19];
    const float* g2  = (const float*)d_in[20];
    const float* be2 = (const float*)d_in[21];
    float* out = (float*)d_out;

    int Btot = in_sizes[0] / EMBED;

    prep_kernel<<<17, 256>>>(Wo1, Wv2, bv2, bo1, Wo2, Wv1, bv1, bo2);
    fused_kernel<<<Btot / TILE_M, 256>>>(v1, v2, g1, be1, g2, be2, out, Btot);
}